// round 1
// baseline (speedup 1.0000x reference)
#include <cuda_runtime.h>

// IFOPooling: h_t = f_t * h_{t-1} + i_t * z_t over seq dim (last, contiguous).
// Shapes: [B=16, H=1024, S=2048] fp32. 16384 independent rows of length 2048.
//
// One CTA per row. 256 threads x 8 elements/thread. Three-phase affine scan:
//   composite of a segment: h_out = F * h_in + X
//   composition: (F1,X1) then (F2,X2) -> (F1*F2, F2*X1 + X2)

#define SEQ 2048
#define TPB 256
#define EPT 8   // elements per thread

__global__ __launch_bounds__(TPB) void ifo_scan_kernel(
    const float* __restrict__ f,
    const float* __restrict__ z,
    const float* __restrict__ ig,
    float* __restrict__ out)
{
    const int row = blockIdx.x;
    const int base = row * SEQ;                 // max 33,554,432-2048 < 2^31
    const int t    = threadIdx.x;
    const int off  = base + t * EPT;

    // ---- Phase 1: coalesced vector loads, local sequential scan ----
    float4 fa = *reinterpret_cast<const float4*>(f  + off);
    float4 fb = *reinterpret_cast<const float4*>(f  + off + 4);
    float4 za = *reinterpret_cast<const float4*>(z  + off);
    float4 zb = *reinterpret_cast<const float4*>(z  + off + 4);
    float4 ia = *reinterpret_cast<const float4*>(ig + off);
    float4 ib = *reinterpret_cast<const float4*>(ig + off + 4);

    float fv[EPT] = {fa.x, fa.y, fa.z, fa.w, fb.x, fb.y, fb.z, fb.w};
    float xv[EPT];
    xv[0] = ia.x * za.x; xv[1] = ia.y * za.y; xv[2] = ia.z * za.z; xv[3] = ia.w * za.w;
    xv[4] = ib.x * zb.x; xv[5] = ib.y * zb.y; xv[6] = ib.z * zb.z; xv[7] = ib.w * zb.w;

    float F = 1.0f, X = 0.0f;   // composite of this thread's segment
    #pragma unroll
    for (int j = 0; j < EPT; j++) {
        X = fmaf(fv[j], X, xv[j]);
        F *= fv[j];
    }

    // ---- Phase 2: inclusive warp scan of composites via shuffle ----
    const unsigned lane = t & 31u;
    const unsigned warp = t >> 5;
    float Fs = F, Xs = X;
    #pragma unroll
    for (int d = 1; d < 32; d <<= 1) {
        float Fo = __shfl_up_sync(0xFFFFFFFFu, Fs, d);
        float Xo = __shfl_up_sync(0xFFFFFFFFu, Xs, d);
        if (lane >= (unsigned)d) {
            Xs = fmaf(Fs, Xo, Xs);   // (Fo,Xo) then (Fs,Xs)
            Fs = Fs * Fo;
        }
    }

    // warp aggregates -> smem
    __shared__ float sF[TPB / 32];
    __shared__ float sX[TPB / 32];
    if (lane == 31) { sF[warp] = Fs; sX[warp] = Xs; }
    __syncthreads();

    // carry from preceding warps (at most 7 iterations, cheap)
    float Xc = 0.0f;   // h value entering this warp
    #pragma unroll
    for (int w = 0; w < TPB / 32; w++) {
        if (w < (int)warp) Xc = fmaf(sF[w], Xc, sX[w]);
    }

    // exclusive-within-warp composite = inclusive of lane-1
    float Fex = __shfl_up_sync(0xFFFFFFFFu, Fs, 1);
    float Xex = __shfl_up_sync(0xFFFFFFFFu, Xs, 1);
    if (lane == 0) { Fex = 1.0f; Xex = 0.0f; }

    // h entering this thread's segment
    float h = fmaf(Fex, Xc, Xex);

    // ---- Phase 3: replay from registers, coalesced vector stores ----
    float r[EPT];
    #pragma unroll
    for (int j = 0; j < EPT; j++) {
        h = fmaf(fv[j], h, xv[j]);
        r[j] = h;
    }
    float4 oa = {r[0], r[1], r[2], r[3]};
    float4 ob = {r[4], r[5], r[6], r[7]};
    *reinterpret_cast<float4*>(out + off)     = oa;
    *reinterpret_cast<float4*>(out + off + 4) = ob;
}

extern "C" void kernel_launch(void* const* d_in, const int* in_sizes, int n_in,
                              void* d_out, int out_size)
{
    const float* f  = (const float*)d_in[0];
    const float* z  = (const float*)d_in[1];
    const float* ig = (const float*)d_in[2];
    float* out = (float*)d_out;

    const int rows = out_size / SEQ;   // B*H = 16384
    ifo_scan_kernel<<<rows, TPB>>>(f, z, ig, out);
}

// round 2
// speedup vs baseline: 1.0041x; 1.0041x over previous
#include <cuda_runtime.h>

// IFOPooling: h_t = f_t * h_{t-1} + i_t * z_t over seq dim (last, contiguous).
// Shapes: [B=16, H=1024, S=2048] fp32. 16384 independent rows of length 2048.
//
// One CTA per row. 256 threads x 8 elements/thread. Three-phase affine scan.
// R2: __launch_bounds__(256,6) to lift occupancy (43->40 regs, 5->6 CTA/SM),
//     streaming loads/stores (.cs) since there is zero data reuse.

#define SEQ 2048
#define TPB 256
#define EPT 8   // elements per thread

__global__ __launch_bounds__(TPB, 6) void ifo_scan_kernel(
    const float* __restrict__ f,
    const float* __restrict__ z,
    const float* __restrict__ ig,
    float* __restrict__ out)
{
    const int row = blockIdx.x;
    const int base = row * SEQ;
    const int t    = threadIdx.x;
    const int off  = base + t * EPT;

    // ---- Phase 1: coalesced streaming vector loads, local sequential scan ----
    float4 fa = __ldcs(reinterpret_cast<const float4*>(f  + off));
    float4 fb = __ldcs(reinterpret_cast<const float4*>(f  + off + 4));
    float4 za = __ldcs(reinterpret_cast<const float4*>(z  + off));
    float4 zb = __ldcs(reinterpret_cast<const float4*>(z  + off + 4));
    float4 ia = __ldcs(reinterpret_cast<const float4*>(ig + off));
    float4 ib = __ldcs(reinterpret_cast<const float4*>(ig + off + 4));

    float fv[EPT] = {fa.x, fa.y, fa.z, fa.w, fb.x, fb.y, fb.z, fb.w};
    float xv[EPT];
    xv[0] = ia.x * za.x; xv[1] = ia.y * za.y; xv[2] = ia.z * za.z; xv[3] = ia.w * za.w;
    xv[4] = ib.x * zb.x; xv[5] = ib.y * zb.y; xv[6] = ib.z * zb.z; xv[7] = ib.w * zb.w;

    float F = 1.0f, X = 0.0f;   // composite of this thread's segment
    #pragma unroll
    for (int j = 0; j < EPT; j++) {
        X = fmaf(fv[j], X, xv[j]);
        F *= fv[j];
    }

    // ---- Phase 2: inclusive warp scan of composites via shuffle ----
    const unsigned lane = t & 31u;
    const unsigned warp = t >> 5;
    float Fs = F, Xs = X;
    #pragma unroll
    for (int d = 1; d < 32; d <<= 1) {
        float Fo = __shfl_up_sync(0xFFFFFFFFu, Fs, d);
        float Xo = __shfl_up_sync(0xFFFFFFFFu, Xs, d);
        if (lane >= (unsigned)d) {
            Xs = fmaf(Fs, Xo, Xs);   // (Fo,Xo) then (Fs,Xs)
            Fs = Fs * Fo;
        }
    }

    // warp aggregates -> smem
    __shared__ float sF[TPB / 32];
    __shared__ float sX[TPB / 32];
    if (lane == 31) { sF[warp] = Fs; sX[warp] = Xs; }
    __syncthreads();

    // carry from preceding warps (at most 7 iterations, cheap)
    float Xc = 0.0f;   // h value entering this warp
    #pragma unroll
    for (int w = 0; w < TPB / 32; w++) {
        if (w < (int)warp) Xc = fmaf(sF[w], Xc, sX[w]);
    }

    // exclusive-within-warp composite = inclusive of lane-1
    float Fex = __shfl_up_sync(0xFFFFFFFFu, Fs, 1);
    float Xex = __shfl_up_sync(0xFFFFFFFFu, Xs, 1);
    if (lane == 0) { Fex = 1.0f; Xex = 0.0f; }

    // h entering this thread's segment
    float h = fmaf(Fex, Xc, Xex);

    // ---- Phase 3: replay from registers, coalesced streaming stores ----
    float r[EPT];
    #pragma unroll
    for (int j = 0; j < EPT; j++) {
        h = fmaf(fv[j], h, xv[j]);
        r[j] = h;
    }
    float4 oa = {r[0], r[1], r[2], r[3]};
    float4 ob = {r[4], r[5], r[6], r[7]};
    __stcs(reinterpret_cast<float4*>(out + off),     oa);
    __stcs(reinterpret_cast<float4*>(out + off + 4), ob);
}

extern "C" void kernel_launch(void* const* d_in, const int* in_sizes, int n_in,
                              void* d_out, int out_size)
{
    const float* f  = (const float*)d_in[0];
    const float* z  = (const float*)d_in[1];
    const float* ig = (const float*)d_in[2];
    float* out = (float*)d_out;

    const int rows = out_size / SEQ;   // B*H = 16384
    ifo_scan_kernel<<<rows, TPB>>>(f, z, ig, out);
}